// round 2
// baseline (speedup 1.0000x reference)
#include <cuda_runtime.h>
#include <cstdint>

#define B_    32
#define C_    64
#define HW_   128
#define NPIX  (HW_*HW_)      // 16384
#define NIMG  (B_*C_)        // 2048

// single 128MB scratch: holds f2 transposed [b,c,w,h], then (f6+f2) transposed in-place
__device__ float g_scratch[(size_t)B_ * C_ * NPIX];

// smem layout for FWHT images: row r at r*130, cols 0..63 at +0, cols 64..127 at +65
// bank(r,h,j) = (2r + j (+1 if j>=64)) mod 32 -> conflict-free for butterfly phases
__device__ __forceinline__ int soff(int r, int j) { return r * 130 + j + (j >> 6); }

__device__ __forceinline__ uint32_t f2tf(float x) {
    uint32_t r;
    asm("cvt.rna.tf32.f32 %0, %1;" : "=r"(r) : "f"(x));
    return r;
}

__device__ __forceinline__ void mma_tf32(float* d, uint32_t a0, uint32_t a1, uint32_t a2, uint32_t a3,
                                         uint32_t b0, uint32_t b1) {
    asm volatile(
        "mma.sync.aligned.m16n8k8.row.col.f32.tf32.tf32.f32 "
        "{%0,%1,%2,%3}, {%4,%5,%6,%7}, {%8,%9}, {%0,%1,%2,%3};\n"
        : "+f"(d[0]), "+f"(d[1]), "+f"(d[2]), "+f"(d[3])
        : "r"(a0), "r"(a1), "r"(a2), "r"(a3), "r"(b0), "r"(b1));
}

__device__ __forceinline__ float softth(float x, float t) {
    float tt = fmaxf(t, 0.0f);
    float m  = fmaxf(fabsf(x) - tt, 0.0f);
    return copysignf(m, x);
}

// ---------------------------------------------------------------------------
// Pass 1 / Pass 3: 2D FWHT of a 128x128 image, output TRANSPOSED, scaled.
// in  layout: [img, a1, a2] (a2 contiguous)
// out layout: [img, a2, a1]
// Transform along a2 then a1. Register-resident butterflies (bit-6 folded at load).
// ---------------------------------------------------------------------------
__global__ void __launch_bounds__(256, 2)
fwht2d_kernel(const float* __restrict__ in, float* __restrict__ out, float scale)
{
    extern __shared__ float s[];
    const int img = blockIdx.x;
    const int tid = threadIdx.x;
    const float* gin  = in  + (size_t)img * NPIX;
    float*       gout = out + (size_t)img * NPIX;

    // phase 0: coalesced gmem -> smem (scalar smem stores: pad breaks vec alignment)
    #pragma unroll
    for (int k = 0; k < 16; k++) {
        int gi = k * 256 + tid;          // float4 index, 4096 total
        int r  = gi >> 5;
        int c  = (gi & 31) * 4;
        float4 v4 = __ldg((const float4*)gin + gi);
        int a = soff(r, c);              // c..c+3 never cross the 64 boundary
        s[a]     = v4.x;
        s[a + 1] = v4.y;
        s[a + 2] = v4.z;
        s[a + 3] = v4.w;
    }
    __syncthreads();

    float reg[64];

    // phase W: transform along last axis. thread = (row r, half)
    {
        int r = tid >> 1, half = tid & 1;
        #pragma unroll
        for (int j = 0; j < 64; j++) {
            float a = s[soff(r, j)];
            float b = s[soff(r, j + 64)];
            reg[j] = half ? (a - b) : (a + b);   // bit-6 butterfly at load
        }
        #pragma unroll
        for (int st = 1; st < 64; st <<= 1) {
            #pragma unroll
            for (int i = 0; i < 64; i++) {
                if ((i & st) == 0) {
                    float a = reg[i], b = reg[i + st];
                    reg[i] = a + b;  reg[i + st] = a - b;
                }
            }
        }
        __syncthreads();   // all reads done before overwrite
        #pragma unroll
        for (int j = 0; j < 64; j++)
            s[soff(r, half * 64 + j)] = reg[j];
    }
    __syncthreads();

    // phase H: transform along first axis. thread = (col w, half hh)
    {
        int w = tid & 127, hh = tid >> 7;
        #pragma unroll
        for (int j = 0; j < 64; j++) {
            float a = s[soff(j, w)];
            float b = s[soff(j + 64, w)];
            reg[j] = hh ? (a - b) : (a + b);
        }
        #pragma unroll
        for (int st = 1; st < 64; st <<= 1) {
            #pragma unroll
            for (int i = 0; i < 64; i++) {
                if ((i & st) == 0) {
                    float a = reg[i], b = reg[i + st];
                    reg[i] = a + b;  reg[i + st] = a - b;
                }
            }
        }
        __syncthreads();
        // write TRANSPOSED: s2[w][h]
        #pragma unroll
        for (int j = 0; j < 64; j++)
            s[soff(w, hh * 64 + j)] = reg[j];
    }
    __syncthreads();

    // final: coalesced smem -> gmem with scale (out layout [a2, a1])
    #pragma unroll
    for (int k = 0; k < 16; k++) {
        int gi = k * 256 + tid;
        int r  = gi >> 5;
        int c  = (gi & 31) * 4;
        int a  = soff(r, c);
        float4 v4 = make_float4(s[a] * scale, s[a + 1] * scale,
                                s[a + 2] * scale, s[a + 3] * scale);
        ((float4*)gout)[gi] = v4;
    }
}

// ---------------------------------------------------------------------------
// Pass 2: per (b,w) tile of 128 pixels (h=0..127), all 64 channels.
// D[128m,128n] = Wstack[128x64] @ f2tile[64x128] via mma.sync tf32,
// then v-scale, soft-threshold, pod-sum, +f2, written back IN PLACE.
// Scratch layout is transposed: f2[b,c,w,h].
// ---------------------------------------------------------------------------
__global__ void __launch_bounds__(256, 2)
podmix_kernel(float* __restrict__ f2, const float* __restrict__ v,
              const float* __restrict__ T, const float* __restrict__ W)
{
    extern __shared__ float sm[];
    float* f2s   = sm;               // [64][132]  = 8448 floats (original fp32 tile)
    float* wsbuf = sm + 8448;        // shared region: ws [128][68]=8704 then buf [64][132]
    float* vs0   = sm + 8448 + 8704; // 128
    float* Ts0   = vs0 + 128;
    float* vs1   = Ts0 + 128;
    float* Ts1   = vs1 + 128;

    const int b   = blockIdx.x >> 7;
    const int w   = blockIdx.x & 127;
    const int tid = threadIdx.x;
    const int wid = tid >> 5;
    const int lane = tid & 31;
    const int gid = lane >> 2;   // 0..7
    const int tig = lane & 3;    // 0..3

    float* gtile = f2 + (((size_t)b * 64) * 128 + w) * 128;   // + c*NPIX + h

    // load f2 tile (coalesced, 512B per channel row)
    #pragma unroll
    for (int k = 0; k < 8; k++) {
        int i = k * 256 + tid;       // 2048 float4
        int c = i >> 5;
        int h = (i & 31) * 4;
        float4 t = __ldg((const float4*)(gtile + (size_t)c * NPIX) + (i & 31));
        *(float4*)&f2s[c * 132 + h] = t;
    }
    // stacked weights [m=pod*64+o][k] -> ws stride 68 (conflict-free frag loads)
    #pragma unroll
    for (int k = 0; k < 32; k++) {
        int i = k * 256 + tid;       // 8192 elements, linear in conv_w
        int m = i >> 6, kk = i & 63;
        wsbuf[m * 68 + kk] = __ldg(W + i);
    }
    // v/T columns for this w (pixel p = w*128+h corresponds to original (h,w))
    if (tid < 128) {
        int h = tid;
        vs0[h] = __ldg(v + h * 128 + w);
        Ts0[h] = __ldg(T + h * 128 + w);
    } else {
        int h = tid - 128;
        vs1[h] = __ldg(v + NPIX + h * 128 + w);
        Ts1[h] = __ldg(T + NPIX + h * 128 + w);
    }
    __syncthreads();

    // warp wid owns m-rows [16*wid, 16*wid+16); warps 0-3 = pod0, 4-7 = pod1
    const int m0 = wid * 16;
    float acc[16][4];
    #pragma unroll
    for (int nb = 0; nb < 16; nb++) {
        acc[nb][0] = 0.f; acc[nb][1] = 0.f; acc[nb][2] = 0.f; acc[nb][3] = 0.f;
    }

    #pragma unroll 1
    for (int kb = 0; kb < 8; kb++) {
        int k0 = kb * 8 + tig;
        uint32_t a0 = f2tf(wsbuf[(m0 + gid)     * 68 + k0]);
        uint32_t a1 = f2tf(wsbuf[(m0 + gid + 8) * 68 + k0]);
        uint32_t a2 = f2tf(wsbuf[(m0 + gid)     * 68 + k0 + 4]);
        uint32_t a3 = f2tf(wsbuf[(m0 + gid + 8) * 68 + k0 + 4]);
        #pragma unroll
        for (int nb = 0; nb < 16; nb++) {
            uint32_t b0 = f2tf(f2s[(kb * 8 + tig)     * 132 + nb * 8 + gid]);
            uint32_t b1 = f2tf(f2s[(kb * 8 + tig + 4) * 132 + nb * 8 + gid]);
            mma_tf32(acc[nb], a0, a1, a2, a3, b0, b1);
        }
    }
    __syncthreads();   // done reading ws region; pod1 may overwrite it as buf

    float* buf = wsbuf;   // [64][132]
    if (wid >= 4) {       // pod 1: soft-threshold, stage to smem
        int o0 = m0 - 64 + gid;
        #pragma unroll
        for (int nb = 0; nb < 16; nb++) {
            int h = nb * 8 + 2 * tig;
            buf[o0 * 132 + h]           = softth(vs1[h]     * acc[nb][0], Ts1[h]);
            buf[o0 * 132 + h + 1]       = softth(vs1[h + 1] * acc[nb][1], Ts1[h + 1]);
            buf[(o0 + 8) * 132 + h]     = softth(vs1[h]     * acc[nb][2], Ts1[h]);
            buf[(o0 + 8) * 132 + h + 1] = softth(vs1[h + 1] * acc[nb][3], Ts1[h + 1]);
        }
    }
    __syncthreads();
    if (wid < 4) {        // pod 0: combine pods, add original f2, store in place
        int o0 = m0 + gid;
        #pragma unroll
        for (int nb = 0; nb < 16; nb++) {
            int h = nb * 8 + 2 * tig;
            float s00 = softth(vs0[h]     * acc[nb][0], Ts0[h]);
            float s01 = softth(vs0[h + 1] * acc[nb][1], Ts0[h + 1]);
            float s10 = softth(vs0[h]     * acc[nb][2], Ts0[h]);
            float s11 = softth(vs0[h + 1] * acc[nb][3], Ts0[h + 1]);
            float2 v0 = make_float2(s00 + buf[o0 * 132 + h]     + f2s[o0 * 132 + h],
                                    s01 + buf[o0 * 132 + h + 1] + f2s[o0 * 132 + h + 1]);
            float2 v1 = make_float2(s10 + buf[(o0 + 8) * 132 + h]     + f2s[(o0 + 8) * 132 + h],
                                    s11 + buf[(o0 + 8) * 132 + h + 1] + f2s[(o0 + 8) * 132 + h + 1]);
            *(float2*)(gtile + (size_t)o0 * NPIX + h)       = v0;
            *(float2*)(gtile + (size_t)(o0 + 8) * NPIX + h) = v1;
        }
    }
}

extern "C" void kernel_launch(void* const* d_in, const int* in_sizes, int n_in,
                              void* d_out, int out_size)
{
    (void)in_sizes; (void)n_in; (void)out_size;
    const float* x = (const float*)d_in[0];
    const float* v = (const float*)d_in[1];
    const float* T = (const float*)d_in[2];
    const float* W = (const float*)d_in[3];
    float* out = (float*)d_out;

    float* scratch = nullptr;
    cudaGetSymbolAddress((void**)&scratch, g_scratch);

    const int smem1 = 128 * 130 * 4;                 // 66560 B
    const int smem2 = (8448 + 8704 + 4 * 128) * 4;   // 70656 B
    cudaFuncSetAttribute(fwht2d_kernel, cudaFuncAttributeMaxDynamicSharedMemorySize, smem1);
    cudaFuncSetAttribute(podmix_kernel, cudaFuncAttributeMaxDynamicSharedMemorySize, smem2);

    // P1: f2_t[b,c,w,h] = FWHT2D(x), transposed
    fwht2d_kernel<<<NIMG, 256, smem1>>>(x, scratch, 1.0f);
    // P2: in place: scratch <- f6 + f2 (transposed domain)
    podmix_kernel<<<B_ * 128, 256, smem2>>>(scratch, v, T, W);
    // P3: out = iFWHT2D(f6 + f2) = f8 + x   (re-transposes back to [h,w])
    fwht2d_kernel<<<NIMG, 256, smem1>>>(scratch, out, 1.0f / 16384.0f);
}

// round 4
// speedup vs baseline: 1.1409x; 1.1409x over previous
#include <cuda_runtime.h>
#include <cstdint>

#define B_    32
#define HW_   128
#define NPIX  16384
#define NIMG  2048

// 128MB scratch: f2 transposed [b,c,w,h], then (f6+f2) in-place
__device__ float g_scratch[(size_t)B_ * 64 * NPIX];

// XOR-swizzled smem layout, stride 128 words (no pad):
// word(r,h) = r*128 + (((h/4 ^ r)&31)<<2) + h%4
__device__ __forceinline__ int sidx(int r, int h) {
    return r * 128 + ((((h >> 2) ^ r) & 31) << 2) + (h & 3);
}
__device__ __forceinline__ int sidx4(int r, int h4) {
    return r * 128 + (((h4 ^ r) & 31) << 2);
}

__device__ __forceinline__ uint32_t f2tf(float x) {
    uint32_t r; asm("cvt.rna.tf32.f32 %0, %1;" : "=r"(r) : "f"(x)); return r;
}
__device__ __forceinline__ float softth(float x, float t) {
    float tt = fmaxf(t, 0.f);
    return copysignf(fmaxf(fabsf(x) - tt, 0.f), x);
}

__device__ __forceinline__ void mma_tf32(float* d, uint32_t a0, uint32_t a1, uint32_t a2, uint32_t a3,
                                         uint32_t b0, uint32_t b1) {
    asm volatile(
        "mma.sync.aligned.m16n8k8.row.col.f32.tf32.tf32.f32 "
        "{%0,%1,%2,%3}, {%4,%5,%6,%7}, {%8,%9}, {%0,%1,%2,%3};\n"
        : "+f"(d[0]), "+f"(d[1]), "+f"(d[2]), "+f"(d[3])
        : "r"(a0), "r"(a1), "r"(a2), "r"(a3), "r"(b0), "r"(b1));
}

// ---------------------------------------------------------------------------
// Pass 1 / Pass 3: 2D FWHT of 128x128 image, output TRANSPOSED, scaled.
// ---------------------------------------------------------------------------
__global__ void __launch_bounds__(256, 2)
fwht2d_kernel(const float* __restrict__ in, float* __restrict__ out, float scale)
{
    extern __shared__ float s[];
    const int img = blockIdx.x;
    const int tid = threadIdx.x;
    const float* gin  = in  + (size_t)img * NPIX;
    float*       gout = out + (size_t)img * NPIX;

    // stage in: gmem float4 -> swizzled smem float4
    #pragma unroll
    for (int k = 0; k < 16; k++) {
        int gi = k * 256 + tid;          // float4 index, 4096 total
        int r  = gi >> 5;
        int c4 = gi & 31;
        float4 v4 = __ldg((const float4*)gin + gi);
        *(float4*)&s[sidx4(r, c4)] = v4;
    }
    __syncthreads();

    float reg[64];

    // phase W: transform along last axis. thread = (row r, half)
    {
        int r = tid >> 1, half = tid & 1;
        #pragma unroll
        for (int j4 = 0; j4 < 16; j4++) {
            float4 a = *(const float4*)&s[sidx4(r, j4)];
            float4 b = *(const float4*)&s[sidx4(r, j4 + 16)];
            if (half) {
                reg[4*j4+0] = a.x - b.x; reg[4*j4+1] = a.y - b.y;
                reg[4*j4+2] = a.z - b.z; reg[4*j4+3] = a.w - b.w;
            } else {
                reg[4*j4+0] = a.x + b.x; reg[4*j4+1] = a.y + b.y;
                reg[4*j4+2] = a.z + b.z; reg[4*j4+3] = a.w + b.w;
            }
        }
        #pragma unroll
        for (int st = 1; st < 64; st <<= 1)
            #pragma unroll
            for (int i = 0; i < 64; i++)
                if ((i & st) == 0) {
                    float a = reg[i], b = reg[i + st];
                    reg[i] = a + b;  reg[i + st] = a - b;
                }
        __syncthreads();
        #pragma unroll
        for (int j4 = 0; j4 < 16; j4++)
            *(float4*)&s[sidx4(r, half * 16 + j4)] =
                make_float4(reg[4*j4], reg[4*j4+1], reg[4*j4+2], reg[4*j4+3]);
    }
    __syncthreads();

    // phase H: transform along first axis. thread = (col w, half hh)
    {
        int w = tid & 127, hh = tid >> 7;
        #pragma unroll
        for (int j = 0; j < 64; j++) {
            float a = s[sidx(j, w)];
            float b = s[sidx(j + 64, w)];
            reg[j] = hh ? (a - b) : (a + b);
        }
        #pragma unroll
        for (int st = 1; st < 64; st <<= 1)
            #pragma unroll
            for (int i = 0; i < 64; i++)
                if ((i & st) == 0) {
                    float a = reg[i], b = reg[i + st];
                    reg[i] = a + b;  reg[i + st] = a - b;
                }
        __syncthreads();
        // write TRANSPOSED row w
        #pragma unroll
        for (int j4 = 0; j4 < 16; j4++)
            *(float4*)&s[sidx4(w, hh * 16 + j4)] =
                make_float4(reg[4*j4], reg[4*j4+1], reg[4*j4+2], reg[4*j4+3]);
    }
    __syncthreads();

    // stage out with scale
    #pragma unroll
    for (int k = 0; k < 16; k++) {
        int gi = k * 256 + tid;
        int r  = gi >> 5;
        int c4 = gi & 31;
        float4 t = *(const float4*)&s[sidx4(r, c4)];
        ((float4*)gout)[gi] = make_float4(t.x*scale, t.y*scale, t.z*scale, t.w*scale);
    }
}

// ---------------------------------------------------------------------------
// Pass 2: mma.sync tf32 GEMM per (b,w) tile, pre-converted operands.
// D[128m x 128n] = Wstack[128 x 64k] @ f2tile[64k x 128n(h)]
// warp tile m32 x n64; epilogue: v-scale, soft-threshold, pod-sum, +f2, in place
// ---------------------------------------------------------------------------
__global__ void __launch_bounds__(256, 2)
podmix_kernel(float* __restrict__ f2, const float* __restrict__ v,
              const float* __restrict__ T, const float* __restrict__ W)
{
    extern __shared__ float sm[];
    float* Bs  = sm;                 // [64 c][132 h] tf32 bits of f2 tile (8448 w)
    float* As  = sm + 8448;          // [128 m][68 k] tf32 weights (8704 w); later pod1 buf [64][132]
    float* vs0 = sm + 8448 + 8704;   // 128
    float* Ts0 = vs0 + 128;
    float* vs1 = Ts0 + 128;
    float* Ts1 = vs1 + 128;

    const int b    = blockIdx.x >> 7;
    const int w    = blockIdx.x & 127;
    const int tid  = threadIdx.x;
    const int wid  = tid >> 5;
    const int lane = tid & 31;
    const int gid  = lane >> 2;   // 0..7
    const int tig  = lane & 3;    // 0..3
    const int mq   = wid & 3;     // m quarter
    const int ch   = wid >> 1 & 0; // placeholder (computed below properly)
    const int chh  = wid >> 2;    // n half: 0 or 1
    const int m0   = mq * 32;
    const int n0   = chh * 64;
    (void)ch;

    float* gtile = f2 + (((size_t)b * 64) * 128 + w) * 128;   // + c*NPIX + h

    uint32_t* Bsu = (uint32_t*)Bs;
    uint32_t* Asu = (uint32_t*)As;

    // stage f2 tile -> Bs as tf32 bits (layout [c][h], stride 132)
    #pragma unroll
    for (int k = 0; k < 8; k++) {
        int i4 = k * 256 + tid;          // 2048 float4
        int c  = i4 >> 5;
        int h4 = i4 & 31;
        float4 t = __ldg((const float4*)(gtile + (size_t)c * NPIX) + h4);
        *(uint4*)&Bsu[c * 132 + h4 * 4] =
            make_uint4(f2tf(t.x), f2tf(t.y), f2tf(t.z), f2tf(t.w));
    }
    // stage stacked weights -> As as tf32 bits (layout [m][k], stride 68)
    #pragma unroll
    for (int k = 0; k < 8; k++) {
        int i4 = k * 256 + tid;          // 2048 float4 over [128 m][64 k]
        int m  = i4 >> 4;
        int kk = (i4 & 15) * 4;
        float4 t = __ldg((const float4*)W + i4);
        *(uint4*)&Asu[m * 68 + kk] =
            make_uint4(f2tf(t.x), f2tf(t.y), f2tf(t.z), f2tf(t.w));
    }
    // v/T columns for this w
    if (tid < 128) {
        vs0[tid] = __ldg(v + tid * 128 + w);
        Ts0[tid] = __ldg(T + tid * 128 + w);
    } else {
        int h = tid - 128;
        vs1[h] = __ldg(v + NPIX + h * 128 + w);
        Ts1[h] = __ldg(T + NPIX + h * 128 + w);
    }
    __syncthreads();

    float acc[16][4];
    #pragma unroll
    for (int i = 0; i < 16; i++) {
        acc[i][0] = 0.f; acc[i][1] = 0.f; acc[i][2] = 0.f; acc[i][3] = 0.f;
    }

    #pragma unroll 1
    for (int kb = 0; kb < 8; kb++) {
        int k0 = kb * 8 + tig;
        uint32_t a[8];
        a[0] = Asu[(m0 + gid)      * 68 + k0];
        a[1] = Asu[(m0 + gid + 8)  * 68 + k0];
        a[2] = Asu[(m0 + gid)      * 68 + k0 + 4];
        a[3] = Asu[(m0 + gid + 8)  * 68 + k0 + 4];
        a[4] = Asu[(m0 + gid + 16) * 68 + k0];
        a[5] = Asu[(m0 + gid + 24) * 68 + k0];
        a[6] = Asu[(m0 + gid + 16) * 68 + k0 + 4];
        a[7] = Asu[(m0 + gid + 24) * 68 + k0 + 4];
        #pragma unroll
        for (int nb = 0; nb < 8; nb++) {
            uint32_t b0 = Bsu[(kb * 8 + tig)     * 132 + n0 + nb * 8 + gid];
            uint32_t b1 = Bsu[(kb * 8 + tig + 4) * 132 + n0 + nb * 8 + gid];
            mma_tf32(acc[nb],     a[0], a[1], a[2], a[3], b0, b1);
            mma_tf32(acc[8 + nb], a[4], a[5], a[6], a[7], b0, b1);
        }
    }
    __syncthreads();   // all LDS of As/Bs done

    const int pod = mq >> 1;              // warps mq 0,1 = pod0; 2,3 = pod1
    const float* vv = pod ? vs1 : vs0;
    const float* tt = pod ? Ts1 : Ts0;
    float* buf = As;                      // pod1 staging [64][132]

    if (pod) {
        #pragma unroll
        for (int t = 0; t < 2; t++) {
            int o = (m0 - 64) + t * 16 + gid;
            #pragma unroll
            for (int nb = 0; nb < 8; nb++) {
                int i = t * 8 + nb;
                int h = n0 + nb * 8 + 2 * tig;
                float2 lo = make_float2(softth(vv[h]   * acc[i][0], tt[h]),
                                        softth(vv[h+1] * acc[i][1], tt[h+1]));
                float2 hi = make_float2(softth(vv[h]   * acc[i][2], tt[h]),
                                        softth(vv[h+1] * acc[i][3], tt[h+1]));
                *(float2*)&buf[o * 132 + h]       = lo;
                *(float2*)&buf[(o + 8) * 132 + h] = hi;
            }
        }
    }
    __syncthreads();

    if (!pod) {
        #pragma unroll
        for (int t = 0; t < 2; t++) {
            int o = m0 + t * 16 + gid;
            #pragma unroll
            for (int nb = 0; nb < 8; nb++) {
                int i = t * 8 + nb;
                int h = n0 + nb * 8 + 2 * tig;
                float2 b0v = *(const float2*)&buf[o * 132 + h];
                float2 b1v = *(const float2*)&buf[(o + 8) * 132 + h];
                float2 f0v = *(const float2*)&Bs[o * 132 + h];        // tf32 f2 (exact f32)
                float2 f1v = *(const float2*)&Bs[(o + 8) * 132 + h];
                float2 r0 = make_float2(
                    softth(vv[h]   * acc[i][0], tt[h])   + b0v.x + f0v.x,
                    softth(vv[h+1] * acc[i][1], tt[h+1]) + b0v.y + f0v.y);
                float2 r1 = make_float2(
                    softth(vv[h]   * acc[i][2], tt[h])   + b1v.x + f1v.x,
                    softth(vv[h+1] * acc[i][3], tt[h+1]) + b1v.y + f1v.y);
                *(float2*)&Bs[o * 132 + h]       = r0;
                *(float2*)&Bs[(o + 8) * 132 + h] = r1;
            }
        }
    }
    __syncthreads();

    // coalesced store back in place
    #pragma unroll
    for (int k = 0; k < 8; k++) {
        int i4 = k * 256 + tid;
        int c  = i4 >> 5;
        int h4 = i4 & 31;
        float4 t = *(const float4*)&Bs[c * 132 + h4 * 4];
        *((float4*)(gtile + (size_t)c * NPIX) + h4) = t;
    }
}

extern "C" void kernel_launch(void* const* d_in, const int* in_sizes, int n_in,
                              void* d_out, int out_size)
{
    (void)in_sizes; (void)n_in; (void)out_size;
    const float* x = (const float*)d_in[0];
    const float* v = (const float*)d_in[1];
    const float* T = (const float*)d_in[2];
    const float* W = (const float*)d_in[3];
    float* out = (float*)d_out;

    float* scratch = nullptr;
    cudaGetSymbolAddress((void**)&scratch, g_scratch);

    const int smem1 = 128 * 128 * 4;                 // 65536 B
    const int smem2 = (8448 + 8704 + 4 * 128) * 4;   // 70656 B
    cudaFuncSetAttribute(fwht2d_kernel, cudaFuncAttributeMaxDynamicSharedMemorySize, smem1);
    cudaFuncSetAttribute(podmix_kernel, cudaFuncAttributeMaxDynamicSharedMemorySize, smem2);

    fwht2d_kernel<<<NIMG, 256, smem1>>>(x, scratch, 1.0f);
    podmix_kernel<<<B_ * 128, 256, smem2>>>(scratch, v, T, W);
    fwht2d_kernel<<<NIMG, 256, smem1>>>(scratch, out, 1.0f / 16384.0f);
}

// round 5
// speedup vs baseline: 1.3623x; 1.1941x over previous
#include <cuda_runtime.h>
#include <cstdint>

#define B_    32
#define HW_   128
#define NPIX  16384
#define NIMG  2048

// 128MB scratch: f2 (tf32-rounded) transposed [b,c,w,h], then (f6+f2) in-place
__device__ float g_scratch[(size_t)B_ * 64 * NPIX];
// pre-converted tf32 weights in per-thread fragment order
__device__ float g_wtf[8192];

// XOR-swizzled smem layout for fwht, stride 128 words (no pad)
__device__ __forceinline__ int sidx(int r, int h) {
    return r * 128 + ((((h >> 2) ^ r) & 31) << 2) + (h & 3);
}
__device__ __forceinline__ int sidx4(int r, int h4) {
    return r * 128 + (((h4 ^ r) & 31) << 2);
}

__device__ __forceinline__ uint32_t f2tf(float x) {
    uint32_t r; asm("cvt.rna.tf32.f32 %0, %1;" : "=r"(r) : "f"(x)); return r;
}
__device__ __forceinline__ float softth(float x, float t) {
    float tt = fmaxf(t, 0.f);
    return copysignf(fmaxf(fabsf(x) - tt, 0.f), x);
}
__device__ __forceinline__ void mma_tf32(float* d, uint32_t a0, uint32_t a1, uint32_t a2, uint32_t a3,
                                         uint32_t b0, uint32_t b1) {
    asm volatile(
        "mma.sync.aligned.m16n8k8.row.col.f32.tf32.tf32.f32 "
        "{%0,%1,%2,%3}, {%4,%5,%6,%7}, {%8,%9}, {%0,%1,%2,%3};\n"
        : "+f"(d[0]), "+f"(d[1]), "+f"(d[2]), "+f"(d[3])
        : "r"(a0), "r"(a1), "r"(a2), "r"(a3), "r"(b0), "r"(b1));
}

// ---------------------------------------------------------------------------
// prep: conv_w -> tf32, fragment-ordered for podmix mainloop
// thread t = (kb,mq,gid,tig); writes 8 floats (a0..a7 for that fragment slot)
// ---------------------------------------------------------------------------
__global__ void prep_kernel(const float* __restrict__ W)
{
    int t = blockIdx.x * 256 + threadIdx.x;
    if (t >= 1024) return;
    int tig = t & 3, gid = (t >> 2) & 7, mq = (t >> 5) & 3, kb = t >> 7;
    int k0 = kb * 8 + tig;
    int r0 = mq * 16 + gid;
    float* o = g_wtf + t * 8;
    o[0] = __uint_as_float(f2tf(__ldg(W + r0 * 64 + k0)));
    o[1] = __uint_as_float(f2tf(__ldg(W + (r0 + 8) * 64 + k0)));
    o[2] = __uint_as_float(f2tf(__ldg(W + r0 * 64 + k0 + 4)));
    o[3] = __uint_as_float(f2tf(__ldg(W + (r0 + 8) * 64 + k0 + 4)));
    int r1 = r0 + 64;
    o[4] = __uint_as_float(f2tf(__ldg(W + r1 * 64 + k0)));
    o[5] = __uint_as_float(f2tf(__ldg(W + (r1 + 8) * 64 + k0)));
    o[6] = __uint_as_float(f2tf(__ldg(W + r1 * 64 + k0 + 4)));
    o[7] = __uint_as_float(f2tf(__ldg(W + (r1 + 8) * 64 + k0 + 4)));
}

// ---------------------------------------------------------------------------
// Pass 1 / Pass 3: 2D FWHT of 128x128 image, output TRANSPOSED, scaled.
// do_round: round output to tf32 (pass 1 only)
// ---------------------------------------------------------------------------
__global__ void __launch_bounds__(256, 2)
fwht2d_kernel(const float* __restrict__ in, float* __restrict__ out,
              float scale, int do_round)
{
    extern __shared__ float s[];
    const int img = blockIdx.x;
    const int tid = threadIdx.x;
    const float* gin  = in  + (size_t)img * NPIX;
    float*       gout = out + (size_t)img * NPIX;

    #pragma unroll
    for (int k = 0; k < 16; k++) {
        int gi = k * 256 + tid;
        int r  = gi >> 5;
        int c4 = gi & 31;
        float4 v4 = __ldg((const float4*)gin + gi);
        *(float4*)&s[sidx4(r, c4)] = v4;
    }
    __syncthreads();

    float reg[64];

    // phase W
    {
        int r = tid >> 1, half = tid & 1;
        #pragma unroll
        for (int j4 = 0; j4 < 16; j4++) {
            float4 a = *(const float4*)&s[sidx4(r, j4)];
            float4 b = *(const float4*)&s[sidx4(r, j4 + 16)];
            if (half) {
                reg[4*j4+0] = a.x - b.x; reg[4*j4+1] = a.y - b.y;
                reg[4*j4+2] = a.z - b.z; reg[4*j4+3] = a.w - b.w;
            } else {
                reg[4*j4+0] = a.x + b.x; reg[4*j4+1] = a.y + b.y;
                reg[4*j4+2] = a.z + b.z; reg[4*j4+3] = a.w + b.w;
            }
        }
        #pragma unroll
        for (int st = 1; st < 64; st <<= 1)
            #pragma unroll
            for (int i = 0; i < 64; i++)
                if ((i & st) == 0) {
                    float a = reg[i], b = reg[i + st];
                    reg[i] = a + b;  reg[i + st] = a - b;
                }
        __syncthreads();
        #pragma unroll
        for (int j4 = 0; j4 < 16; j4++)
            *(float4*)&s[sidx4(r, half * 16 + j4)] =
                make_float4(reg[4*j4], reg[4*j4+1], reg[4*j4+2], reg[4*j4+3]);
    }
    __syncthreads();

    // phase H (writes transposed)
    {
        int w = tid & 127, hh = tid >> 7;
        #pragma unroll
        for (int j = 0; j < 64; j++) {
            float a = s[sidx(j, w)];
            float b = s[sidx(j + 64, w)];
            reg[j] = hh ? (a - b) : (a + b);
        }
        #pragma unroll
        for (int st = 1; st < 64; st <<= 1)
            #pragma unroll
            for (int i = 0; i < 64; i++)
                if ((i & st) == 0) {
                    float a = reg[i], b = reg[i + st];
                    reg[i] = a + b;  reg[i + st] = a - b;
                }
        __syncthreads();
        #pragma unroll
        for (int j4 = 0; j4 < 16; j4++)
            *(float4*)&s[sidx4(w, hh * 16 + j4)] =
                make_float4(reg[4*j4], reg[4*j4+1], reg[4*j4+2], reg[4*j4+3]);
    }
    __syncthreads();

    if (do_round) {
        #pragma unroll
        for (int k = 0; k < 16; k++) {
            int gi = k * 256 + tid;
            int r  = gi >> 5;
            int c4 = gi & 31;
            float4 t = *(const float4*)&s[sidx4(r, c4)];
            float4 o = make_float4(__uint_as_float(f2tf(t.x)), __uint_as_float(f2tf(t.y)),
                                   __uint_as_float(f2tf(t.z)), __uint_as_float(f2tf(t.w)));
            ((float4*)gout)[gi] = o;
        }
    } else {
        #pragma unroll
        for (int k = 0; k < 16; k++) {
            int gi = k * 256 + tid;
            int r  = gi >> 5;
            int c4 = gi & 31;
            float4 t = *(const float4*)&s[sidx4(r, c4)];
            ((float4*)gout)[gi] = make_float4(t.x*scale, t.y*scale, t.z*scale, t.w*scale);
        }
    }
}

// ---------------------------------------------------------------------------
// Pass 2: mma.sync tf32 per (b,w) tile. Pod-paired warp tiling (register
// combine), A direct from g_wtf (L1-hot), B pure-copy staging (pre-rounded).
// ---------------------------------------------------------------------------
__global__ void __launch_bounds__(256, 2)
podmix_kernel(float* __restrict__ f2, const float* __restrict__ v,
              const float* __restrict__ T)
{
    __shared__ float sm[9216];
    float*    Bs  = sm;               // [64 c][136 h] tf32 bits of f2 tile
    uint32_t* Bsu = (uint32_t*)sm;
    float*    vs0 = sm + 8704;
    float*    Ts0 = vs0 + 128;
    float*    vs1 = Ts0 + 128;
    float*    Ts1 = vs1 + 128;

    const int b    = blockIdx.x >> 7;
    const int w    = blockIdx.x & 127;
    const int tid  = threadIdx.x;
    const int wid  = tid >> 5;
    const int lane = tid & 31;
    const int gid  = lane >> 2;   // 0..7
    const int tig  = lane & 3;    // 0..3
    const int mq   = wid & 3;     // o-quarter (16 rows)
    const int nh   = wid >> 2;    // h half

    float* gtile = f2 + (((size_t)b * 64) * 128 + w) * 128;   // + c*NPIX + h

    // stage f2 tile (already tf32 bits) -> Bs, pure copy
    #pragma unroll
    for (int k = 0; k < 8; k++) {
        int i4 = k * 256 + tid;          // 2048 float4
        int c  = i4 >> 5;
        int h4 = i4 & 31;
        float4 t = __ldg((const float4*)(gtile + (size_t)c * NPIX) + h4);
        *(float4*)&Bs[c * 136 + h4 * 4] = t;
    }
    // v/T columns for this w
    if (tid < 128) {
        vs0[tid] = __ldg(v + tid * 128 + w);
        Ts0[tid] = __ldg(T + tid * 128 + w);
    } else {
        int h = tid - 128;
        vs1[h] = __ldg(v + NPIX + h * 128 + w);
        Ts1[h] = __ldg(T + NPIX + h * 128 + w);
    }
    __syncthreads();

    float acc[16][4];
    #pragma unroll
    for (int i = 0; i < 16; i++) {
        acc[i][0] = 0.f; acc[i][1] = 0.f; acc[i][2] = 0.f; acc[i][3] = 0.f;
    }

    const float4* Aw = (const float4*)g_wtf;

    #pragma unroll
    for (int kb = 0; kb < 8; kb++) {
        int ai = (((kb * 4 + mq) * 8 + gid) * 4 + tig) * 2;
        float4 lo = __ldg(Aw + ai);
        float4 hi = __ldg(Aw + ai + 1);
        uint32_t a0 = __float_as_uint(lo.x), a1 = __float_as_uint(lo.y);
        uint32_t a2 = __float_as_uint(lo.z), a3 = __float_as_uint(lo.w);
        uint32_t a4 = __float_as_uint(hi.x), a5 = __float_as_uint(hi.y);
        uint32_t a6 = __float_as_uint(hi.z), a7 = __float_as_uint(hi.w);
        int r0 = (kb * 8 + tig) * 136 + nh * 64 + gid;
        int r1 = r0 + 4 * 136;
        #pragma unroll
        for (int nb = 0; nb < 8; nb++) {
            uint32_t b0 = Bsu[r0 + nb * 8];
            uint32_t b1 = Bsu[r1 + nb * 8];
            mma_tf32(acc[nb],     a0, a1, a2, a3, b0, b1);   // pod 0
            mma_tf32(acc[8 + nb], a4, a5, a6, a7, b0, b1);   // pod 1
        }
    }
    __syncthreads();   // all B reads done before in-place overwrite

    // epilogue: combine pods in registers, add f2, write back into Bs
    {
        const int o = mq * 16 + gid;
        #pragma unroll
        for (int nb = 0; nb < 8; nb++) {
            int h = nh * 64 + nb * 8 + 2 * tig;
            float v0h = vs0[h], v0h1 = vs0[h+1], t0h = Ts0[h], t0h1 = Ts0[h+1];
            float v1h = vs1[h], v1h1 = vs1[h+1], t1h = Ts1[h], t1h1 = Ts1[h+1];
            float2 f0 = *(const float2*)&Bs[o * 136 + h];
            float2 f1 = *(const float2*)&Bs[(o + 8) * 136 + h];
            float2 r0 = make_float2(
                softth(v0h  * acc[nb][0], t0h)  + softth(v1h  * acc[8+nb][0], t1h)  + f0.x,
                softth(v0h1 * acc[nb][1], t0h1) + softth(v1h1 * acc[8+nb][1], t1h1) + f0.y);
            float2 r1 = make_float2(
                softth(v0h  * acc[nb][2], t0h)  + softth(v1h  * acc[8+nb][2], t1h)  + f1.x,
                softth(v0h1 * acc[nb][3], t0h1) + softth(v1h1 * acc[8+nb][3], t1h1) + f1.y);
            *(float2*)&Bs[o * 136 + h]       = r0;
            *(float2*)&Bs[(o + 8) * 136 + h] = r1;
        }
    }
    __syncthreads();

    // coalesced store back in place
    #pragma unroll
    for (int k = 0; k < 8; k++) {
        int i4 = k * 256 + tid;
        int c  = i4 >> 5;
        int h4 = i4 & 31;
        float4 t = *(const float4*)&Bs[c * 136 + h4 * 4];
        *((float4*)(gtile + (size_t)c * NPIX) + h4) = t;
    }
}

extern "C" void kernel_launch(void* const* d_in, const int* in_sizes, int n_in,
                              void* d_out, int out_size)
{
    (void)in_sizes; (void)n_in; (void)out_size;
    const float* x = (const float*)d_in[0];
    const float* v = (const float*)d_in[1];
    const float* T = (const float*)d_in[2];
    const float* W = (const float*)d_in[3];
    float* out = (float*)d_out;

    float* scratch = nullptr;
    cudaGetSymbolAddress((void**)&scratch, g_scratch);

    const int smem1 = 128 * 128 * 4;   // 65536 B
    cudaFuncSetAttribute(fwht2d_kernel, cudaFuncAttributeMaxDynamicSharedMemorySize, smem1);

    prep_kernel<<<4, 256>>>(W);
    fwht2d_kernel<<<NIMG, 256, smem1>>>(x, scratch, 1.0f, 1);
    podmix_kernel<<<B_ * 128, 256>>>(scratch, v, T);
    fwht2d_kernel<<<NIMG, 256, smem1>>>(scratch, out, 1.0f / 16384.0f, 0);
}